// round 1
// baseline (speedup 1.0000x reference)
#include <cuda_runtime.h>
#include <cuda_bf16.h>
#include <math.h>

// Problem constants
#define BB 8192
#define NN 12
#define HH 512
#define TWO_H 1024
#define VV 256
#define LN_EPS 1e-5f

// Intermediate activations: act[n][b][0:1024], fp32. 402 MB static device scratch.
__device__ float g_act[(size_t)NN * BB * TWO_H];

// ---------------------------------------------------------------------------
// Kernel 1: gather + exclusive prefix sum + LayerNorm + exact GELU
// One CTA per batch row b. 256 threads; each thread owns 4 contiguous dims of
// the 1024-dim concat vector. Threads 0..127 own the ctx half (constant over
// n), threads 128..255 own the running prefix-sum half (registers).
// ---------------------------------------------------------------------------
__global__ void __launch_bounds__(256) act_kernel(
    const float* __restrict__ input_embedding,  // (B, H)
    const int* __restrict__ features,           // (B, N)
    const float* __restrict__ emb_tables,       // (N, V, H)
    const float* __restrict__ ln_gamma,         // (2H,)
    const float* __restrict__ ln_beta)          // (2H,)
{
    const int b = blockIdx.x;
    const int tid = threadIdx.x;
    const int i = tid * 4;           // dim offset in [0,1024)
    const bool is_ctx = (tid < 128);

    __shared__ float sh_s[8];
    __shared__ float sh_q[8];
    __shared__ float sh_mu, sh_rstd;

    float4 vals;
    if (is_ctx) {
        vals = *reinterpret_cast<const float4*>(input_embedding + (size_t)b * HH + i);
    } else {
        vals = make_float4(0.f, 0.f, 0.f, 0.f);
    }
    const float4 g  = *reinterpret_cast<const float4*>(ln_gamma + i);
    const float4 be = *reinterpret_cast<const float4*>(ln_beta + i);

    const float inv = 1.0f / (float)TWO_H;

    for (int n = 0; n < NN; n++) {
        // local partial sums
        float s1 = vals.x + vals.y + vals.z + vals.w;
        float s2 = vals.x * vals.x + vals.y * vals.y + vals.z * vals.z + vals.w * vals.w;
        // warp reduce
        #pragma unroll
        for (int o = 16; o > 0; o >>= 1) {
            s1 += __shfl_xor_sync(0xFFFFFFFFu, s1, o);
            s2 += __shfl_xor_sync(0xFFFFFFFFu, s2, o);
        }
        if ((tid & 31) == 0) { sh_s[tid >> 5] = s1; sh_q[tid >> 5] = s2; }
        __syncthreads();
        if (tid == 0) {
            float ta = 0.f, tb = 0.f;
            #pragma unroll
            for (int w = 0; w < 8; w++) { ta += sh_s[w]; tb += sh_q[w]; }
            float mu  = ta * inv;
            float var = tb * inv - mu * mu;
            sh_mu = mu;
            sh_rstd = rsqrtf(var + LN_EPS);
        }
        __syncthreads();
        const float mu = sh_mu, rstd = sh_rstd;

        // normalize + affine + exact GELU
        float4 y;
        y.x = (vals.x - mu) * rstd * g.x + be.x;
        y.y = (vals.y - mu) * rstd * g.y + be.y;
        y.z = (vals.z - mu) * rstd * g.z + be.z;
        y.w = (vals.w - mu) * rstd * g.w + be.w;
        float4 a;
        a.x = 0.5f * y.x * (1.0f + erff(y.x * 0.70710678118654752f));
        a.y = 0.5f * y.y * (1.0f + erff(y.y * 0.70710678118654752f));
        a.z = 0.5f * y.z * (1.0f + erff(y.z * 0.70710678118654752f));
        a.w = 0.5f * y.w * (1.0f + erff(y.w * 0.70710678118654752f));

        *reinterpret_cast<float4*>(g_act + ((size_t)n * BB + b) * TWO_H + i) = a;

        // advance the exclusive prefix sum with emb_tables[n, features[b,n], :]
        if (!is_ctx) {
            const int feat = features[b * NN + n];
            const float4 e = *reinterpret_cast<const float4*>(
                emb_tables + ((size_t)n * VV + feat) * HH + (i - HH));
            vals.x += e.x; vals.y += e.y; vals.z += e.z; vals.w += e.w;
        }
        // NOTE: reduction barriers above also order smem reuse across iterations
    }
}

// ---------------------------------------------------------------------------
// Kernel 2: 12 independent GEMMs  C[n] = act[n] (8192x1024) * W[n] (1024x256)
// Classic fp32 register-blocked sgemm: CTA tile 128x128, BK=16, 256 threads,
// 8x8 micro-tile per thread. Grid: (vtile=2, btile=64, n=12).
// ---------------------------------------------------------------------------
__global__ void __launch_bounds__(256) gemm_kernel(
    const float* __restrict__ pred_W,   // (N, 2H, V)
    const float* __restrict__ pred_b,   // (N, V)
    float* __restrict__ out)            // (B, N, V)
{
    const int vtile = blockIdx.x;   // 0..1
    const int btile = blockIdx.y;   // 0..63
    const int n     = blockIdx.z;   // 0..11

    const float* A  = g_act + (size_t)n * BB * TWO_H + (size_t)btile * 128 * TWO_H;
    const float* Bm = pred_W + (size_t)n * TWO_H * VV + vtile * 128;

    __shared__ float As[16 * 128];
    __shared__ float Bs[16 * 128];

    const int tid = threadIdx.x;
    // A load: 128 rows x 16 k per chunk, 2 float4 per thread
    const int a_row  = tid >> 2;        // 0..63 (second load +64)
    const int a_col4 = tid & 3;         // k-offset = a_col4*4
    // B load: 16 k x 128 v per chunk, 2 float4 per thread
    const int b_k  = tid >> 5;          // 0..7 (second load +8)
    const int b_v4 = tid & 31;          // v-offset = b_v4*4

    const int tm = (tid >> 4) * 8;      // 0..120
    const int tn = (tid & 15) * 8;      // 0..120

    float acc[8][8];
    #pragma unroll
    for (int ii = 0; ii < 8; ii++)
        #pragma unroll
        for (int jj = 0; jj < 8; jj++) acc[ii][jj] = 0.f;

    for (int k0 = 0; k0 < TWO_H; k0 += 16) {
        const float4 a0 = *reinterpret_cast<const float4*>(A + (size_t)a_row * TWO_H + k0 + a_col4 * 4);
        const float4 a1 = *reinterpret_cast<const float4*>(A + (size_t)(a_row + 64) * TWO_H + k0 + a_col4 * 4);
        const float4 b0 = *reinterpret_cast<const float4*>(Bm + (size_t)(k0 + b_k) * VV + b_v4 * 4);
        const float4 b1 = *reinterpret_cast<const float4*>(Bm + (size_t)(k0 + b_k + 8) * VV + b_v4 * 4);

        __syncthreads();  // previous tile consumed
        As[(a_col4 * 4 + 0) * 128 + a_row] = a0.x;
        As[(a_col4 * 4 + 1) * 128 + a_row] = a0.y;
        As[(a_col4 * 4 + 2) * 128 + a_row] = a0.z;
        As[(a_col4 * 4 + 3) * 128 + a_row] = a0.w;
        As[(a_col4 * 4 + 0) * 128 + a_row + 64] = a1.x;
        As[(a_col4 * 4 + 1) * 128 + a_row + 64] = a1.y;
        As[(a_col4 * 4 + 2) * 128 + a_row + 64] = a1.z;
        As[(a_col4 * 4 + 3) * 128 + a_row + 64] = a1.w;
        *reinterpret_cast<float4*>(&Bs[b_k * 128 + b_v4 * 4]) = b0;
        *reinterpret_cast<float4*>(&Bs[(b_k + 8) * 128 + b_v4 * 4]) = b1;
        __syncthreads();

        #pragma unroll
        for (int kk = 0; kk < 16; kk++) {
            const float4 av0 = *reinterpret_cast<const float4*>(&As[kk * 128 + tm]);
            const float4 av1 = *reinterpret_cast<const float4*>(&As[kk * 128 + tm + 4]);
            const float4 bv0 = *reinterpret_cast<const float4*>(&Bs[kk * 128 + tn]);
            const float4 bv1 = *reinterpret_cast<const float4*>(&Bs[kk * 128 + tn + 4]);
            const float ar[8] = {av0.x, av0.y, av0.z, av0.w, av1.x, av1.y, av1.z, av1.w};
            const float br[8] = {bv0.x, bv0.y, bv0.z, bv0.w, bv1.x, bv1.y, bv1.z, bv1.w};
            #pragma unroll
            for (int ii = 0; ii < 8; ii++)
                #pragma unroll
                for (int jj = 0; jj < 8; jj++)
                    acc[ii][jj] = fmaf(ar[ii], br[jj], acc[ii][jj]);
        }
    }

    // epilogue: add bias, store to out[b][n][v]
    const float* bp = pred_b + n * VV + vtile * 128 + tn;
    float bias[8];
    #pragma unroll
    for (int jj = 0; jj < 8; jj++) bias[jj] = bp[jj];

    #pragma unroll
    for (int ii = 0; ii < 8; ii++) {
        const size_t m = (size_t)(btile * 128 + tm + ii);
        float* o = out + (m * NN + n) * VV + vtile * 128 + tn;
        float4 r0, r1;
        r0.x = acc[ii][0] + bias[0];
        r0.y = acc[ii][1] + bias[1];
        r0.z = acc[ii][2] + bias[2];
        r0.w = acc[ii][3] + bias[3];
        r1.x = acc[ii][4] + bias[4];
        r1.y = acc[ii][5] + bias[5];
        r1.z = acc[ii][6] + bias[6];
        r1.w = acc[ii][7] + bias[7];
        *reinterpret_cast<float4*>(o)     = r0;
        *reinterpret_cast<float4*>(o + 4) = r1;
    }
}

extern "C" void kernel_launch(void* const* d_in, const int* in_sizes, int n_in,
                              void* d_out, int out_size)
{
    const float* input_embedding = (const float*)d_in[0];  // (B, H)
    const int*   features        = (const int*)d_in[1];    // (B, N)
    const float* emb_tables      = (const float*)d_in[2];  // (N, V, H)
    const float* ln_gamma        = (const float*)d_in[3];  // (2H,)
    const float* ln_beta         = (const float*)d_in[4];  // (2H,)
    const float* pred_W          = (const float*)d_in[5];  // (N, 2H, V)
    const float* pred_b          = (const float*)d_in[6];  // (N, V)
    float* out = (float*)d_out;                            // (B, N, V)

    act_kernel<<<BB, 256>>>(input_embedding, features, emb_tables, ln_gamma, ln_beta);

    dim3 grid(2, 64, 12);
    gemm_kernel<<<grid, 256>>>(pred_W, pred_b, out);
}

// round 3
// speedup vs baseline: 2.1194x; 2.1194x over previous
#include <cuda_runtime.h>
#include <cuda_bf16.h>
#include <math.h>
#include <stdint.h>

// Problem constants
#define BB 8192
#define NN 12
#define HH 512
#define TWO_H 1024
#define VV 256
#define LN_EPS 1e-5f

// ---------------------------------------------------------------------------
// Device scratch: bf16 hi/lo activations + W^T hi/lo (no allocations allowed)
// ---------------------------------------------------------------------------
__device__ __align__(1024) __nv_bfloat16 g_a_hi[(size_t)NN * BB * TWO_H];
__device__ __align__(1024) __nv_bfloat16 g_a_lo[(size_t)NN * BB * TWO_H];
__device__ __align__(1024) __nv_bfloat16 g_w_hi[(size_t)NN * VV * TWO_H];
__device__ __align__(1024) __nv_bfloat16 g_w_lo[(size_t)NN * VV * TWO_H];

// ---------------------------------------------------------------------------
// PTX helpers (base-PTX only: cp.async, ldmatrix, mma.sync — all sm_80+)
// ---------------------------------------------------------------------------
__device__ __forceinline__ uint32_t smem_u32(const void* p) {
    uint32_t a;
    asm("{ .reg .u64 t; cvta.to.shared.u64 t, %1; cvt.u32.u64 %0, t; }" : "=r"(a) : "l"(p));
    return a;
}
__device__ __forceinline__ void cp_async16(uint32_t dst, const void* src) {
    asm volatile("cp.async.cg.shared.global [%0], [%1], 16;" :: "r"(dst), "l"(src) : "memory");
}
#define CP_ASYNC_COMMIT() asm volatile("cp.async.commit_group;" ::: "memory")

__device__ __forceinline__ void ldsm_x4(uint32_t& r0, uint32_t& r1, uint32_t& r2, uint32_t& r3,
                                        uint32_t addr) {
    asm volatile("ldmatrix.sync.aligned.m8n8.x4.shared.b16 {%0,%1,%2,%3}, [%4];"
                 : "=r"(r0), "=r"(r1), "=r"(r2), "=r"(r3) : "r"(addr));
}
__device__ __forceinline__ void mma_bf16(float* d, const uint32_t* a, const uint32_t* b) {
    asm volatile(
        "mma.sync.aligned.m16n8k16.row.col.f32.bf16.bf16.f32 "
        "{%0,%1,%2,%3}, {%4,%5,%6,%7}, {%8,%9}, {%0,%1,%2,%3};"
        : "+f"(d[0]), "+f"(d[1]), "+f"(d[2]), "+f"(d[3])
        : "r"(a[0]), "r"(a[1]), "r"(a[2]), "r"(a[3]), "r"(b[0]), "r"(b[1]));
}

#define SWZ128(o) ((o) ^ (((o) >> 3) & 0x70))

__device__ __forceinline__ void split_bf16(float a, __nv_bfloat16& hi, __nv_bfloat16& lo) {
    hi = __float2bfloat16(a);
    lo = __float2bfloat16(a - __bfloat162float(hi));
}

// ---------------------------------------------------------------------------
// Kernel 1: gather + exclusive prefix sum + LayerNorm + exact GELU -> bf16 hi/lo
// One CTA per batch row b. 256 threads x 4 dims each.
// ---------------------------------------------------------------------------
__global__ void __launch_bounds__(256) act_kernel(
    const float* __restrict__ input_embedding,  // (B, H)
    const int* __restrict__ features,           // (B, N)
    const float* __restrict__ emb_tables,       // (N, V, H)
    const float* __restrict__ ln_gamma,         // (2H,)
    const float* __restrict__ ln_beta)          // (2H,)
{
    const int b = blockIdx.x;
    const int tid = threadIdx.x;
    const int i = tid * 4;
    const bool is_ctx = (tid < 128);

    __shared__ float sh_s[8];
    __shared__ float sh_q[8];
    __shared__ float sh_mu, sh_rstd;

    float4 vals;
    if (is_ctx) {
        vals = *reinterpret_cast<const float4*>(input_embedding + (size_t)b * HH + i);
    } else {
        vals = make_float4(0.f, 0.f, 0.f, 0.f);
    }
    const float4 g  = *reinterpret_cast<const float4*>(ln_gamma + i);
    const float4 be = *reinterpret_cast<const float4*>(ln_beta + i);

    const float inv = 1.0f / (float)TWO_H;

    for (int n = 0; n < NN; n++) {
        float s1 = vals.x + vals.y + vals.z + vals.w;
        float s2 = vals.x * vals.x + vals.y * vals.y + vals.z * vals.z + vals.w * vals.w;
        #pragma unroll
        for (int o = 16; o > 0; o >>= 1) {
            s1 += __shfl_xor_sync(0xFFFFFFFFu, s1, o);
            s2 += __shfl_xor_sync(0xFFFFFFFFu, s2, o);
        }
        if ((tid & 31) == 0) { sh_s[tid >> 5] = s1; sh_q[tid >> 5] = s2; }
        __syncthreads();
        if (tid == 0) {
            float ta = 0.f, tb = 0.f;
            #pragma unroll
            for (int w = 0; w < 8; w++) { ta += sh_s[w]; tb += sh_q[w]; }
            float mu  = ta * inv;
            float var = tb * inv - mu * mu;
            sh_mu = mu;
            sh_rstd = rsqrtf(var + LN_EPS);
        }
        __syncthreads();
        const float mu = sh_mu, rstd = sh_rstd;

        float yv[4] = {vals.x, vals.y, vals.z, vals.w};
        float gv[4] = {g.x, g.y, g.z, g.w};
        float bv[4] = {be.x, be.y, be.z, be.w};
        __nv_bfloat16 h4[4], l4[4];
        #pragma unroll
        for (int j = 0; j < 4; j++) {
            float y = (yv[j] - mu) * rstd * gv[j] + bv[j];
            float a = 0.5f * y * (1.0f + erff(y * 0.70710678118654752f));
            split_bf16(a, h4[j], l4[j]);
        }
        const size_t ofs = ((size_t)n * BB + b) * TWO_H + i;
        *reinterpret_cast<uint2*>(g_a_hi + ofs) = *reinterpret_cast<uint2*>(h4);
        *reinterpret_cast<uint2*>(g_a_lo + ofs) = *reinterpret_cast<uint2*>(l4);

        if (!is_ctx) {
            const int feat = features[b * NN + n];
            const float4 e = *reinterpret_cast<const float4*>(
                emb_tables + ((size_t)n * VV + feat) * HH + (i - HH));
            vals.x += e.x; vals.y += e.y; vals.z += e.z; vals.w += e.w;
        }
    }
}

// ---------------------------------------------------------------------------
// Kernel 2: transpose + bf16-split pred_W (N,2H,V) -> W^T hi/lo (N,V,2H)
// ---------------------------------------------------------------------------
__global__ void __launch_bounds__(256) wconv_kernel(const float* __restrict__ pred_W)
{
    __shared__ float tile[32][33];
    const int n  = blockIdx.z;
    const int k0 = blockIdx.x * 32;
    const int v0 = blockIdx.y * 32;
    const int tx = threadIdx.x, ty = threadIdx.y;

    #pragma unroll
    for (int r = 0; r < 4; r++) {
        const int k = k0 + ty + r * 8;
        tile[ty + r * 8][tx] = pred_W[((size_t)n * TWO_H + k) * VV + v0 + tx];
    }
    __syncthreads();
    #pragma unroll
    for (int r = 0; r < 4; r++) {
        const int v = v0 + ty + r * 8;
        const float w = tile[tx][ty + r * 8];
        __nv_bfloat16 hi, lo;
        split_bf16(w, hi, lo);
        const size_t idx = ((size_t)n * VV + v) * TWO_H + k0 + tx;
        g_w_hi[idx] = hi;
        g_w_lo[idx] = lo;
    }
}

// ---------------------------------------------------------------------------
// Kernel 3: mma.sync bf16 GEMM with 3-term split accumulation.
// CTA tile 128(M)x128(N), K-chunk 64, double-buffered cp.async.
// 8 warps: warpM = wid&3 (32 rows each), warpN = wid>>2 (64 cols each).
// C = Ah*Bh + Ah*Bl + Al*Bh (fp32 accum).
// ---------------------------------------------------------------------------
#define KCH 64
#define NCHUNK (TWO_H / KCH)            // 16
#define TILE_BYTES (128 * 128)          // 16KB each (128 rows x 64 bf16)
#define STAGE_BYTES (4 * TILE_BYTES)    // Ah, Al, Bh, Bl = 64KB
#define GEMM_DYN_SMEM (2 * STAGE_BYTES) // 128KB

__global__ void __launch_bounds__(256, 1) gemm_mma_kernel(
    const float* __restrict__ pred_b,   // (N, V)
    float* __restrict__ out)            // (B, N, V)
{
    extern __shared__ __align__(1024) char dynsmem[];
    const int vtile = blockIdx.x;       // 0..1
    const int mtile = blockIdx.y;       // 0..63
    const int n     = blockIdx.z;       // 0..11
    const int tid = threadIdx.x;
    const int wid = tid >> 5;
    const int lid = tid & 31;
    const int warpM = wid & 3;          // 0..3 -> 32 rows
    const int warpN = wid >> 2;         // 0..1 -> 64 cols

    const uint32_t base = smem_u32(dynsmem);

    const __nv_bfloat16* Ah = g_a_hi + ((size_t)n * BB + (size_t)mtile * 128) * TWO_H;
    const __nv_bfloat16* Al = g_a_lo + ((size_t)n * BB + (size_t)mtile * 128) * TWO_H;
    const __nv_bfloat16* Bh = g_w_hi + ((size_t)n * VV + (size_t)vtile * 128) * TWO_H;
    const __nv_bfloat16* Bl = g_w_lo + ((size_t)n * VV + (size_t)vtile * 128) * TWO_H;

    // cp.async indexing: each 16KB tile = 128 rows x 8 segs of 16B.
    // Each thread loads 4 segs per tile: s = t*256+tid, row=s>>3, seg=s&7.
    const int l_row[4] = { (0 * 256 + tid) >> 3, (1 * 256 + tid) >> 3,
                           (2 * 256 + tid) >> 3, (3 * 256 + tid) >> 3 };
    const int l_seg = tid & 7;

    float acc[2][8][4];
    #pragma unroll
    for (int f = 0; f < 2; f++)
        #pragma unroll
        for (int nf = 0; nf < 8; nf++)
            #pragma unroll
            for (int j = 0; j < 4; j++) acc[f][nf][j] = 0.f;

    // ldmatrix lane addressing (byte offsets within a 16KB tile)
    const int lrow = lid & 15;          // row within 16-row group
    const int khalf = lid >> 4;         // 0/1 -> k 0-7 / 8-15

    #define LOAD_STAGE(c, buf) do { \
        const uint32_t sAh = base + (buf) * STAGE_BYTES; \
        const uint32_t sAl = sAh + TILE_BYTES; \
        const uint32_t sBh = sAl + TILE_BYTES; \
        const uint32_t sBl = sBh + TILE_BYTES; \
        const int kofs = (c) * KCH; \
        _Pragma("unroll") \
        for (int t = 0; t < 4; t++) { \
            const int row = l_row[t]; \
            const uint32_t d = SWZ128(row * 128 + l_seg * 16); \
            const size_t go = (size_t)row * TWO_H + kofs + l_seg * 8; \
            cp_async16(sAh + d, Ah + go); \
            cp_async16(sAl + d, Al + go); \
            cp_async16(sBh + d, Bh + go); \
            cp_async16(sBl + d, Bl + go); \
        } \
        CP_ASYNC_COMMIT(); \
    } while (0)

    LOAD_STAGE(0, 0);

    for (int c = 0; c < NCHUNK; c++) {
        if (c + 1 < NCHUNK) {
            LOAD_STAGE(c + 1, (c + 1) & 1);
            asm volatile("cp.async.wait_group 1;" ::: "memory");
        } else {
            asm volatile("cp.async.wait_group 0;" ::: "memory");
        }
        __syncthreads();

        const uint32_t sAh = base + (c & 1) * STAGE_BYTES;
        const uint32_t sAl = sAh + TILE_BYTES;
        const uint32_t sBh = sAl + TILE_BYTES;
        const uint32_t sBl = sBh + TILE_BYTES;

        #pragma unroll
        for (int ks = 0; ks < 4; ks++) {
            uint32_t ah[2][4], al[2][4], bh[8][2], bl[8][2];
            // A fragments: rows warpM*32 + f*16 + lrow, k-bytes ks*32 + khalf*16
            #pragma unroll
            for (int f = 0; f < 2; f++) {
                const int row = warpM * 32 + f * 16 + lrow;
                const uint32_t d = SWZ128(row * 128 + ks * 32 + khalf * 16);
                ldsm_x4(ah[f][0], ah[f][1], ah[f][2], ah[f][3], sAh + d);
                ldsm_x4(al[f][0], al[f][1], al[f][2], al[f][3], sAl + d);
            }
            // B fragments: rows warpN*64 + g*16 + lrow
            #pragma unroll
            for (int gB = 0; gB < 4; gB++) {
                const int row = warpN * 64 + gB * 16 + lrow;
                const uint32_t d = SWZ128(row * 128 + ks * 32 + khalf * 16);
                uint32_t t0, t1, t2, t3;
                ldsm_x4(t0, t1, t2, t3, sBh + d);
                bh[gB * 2][0] = t0; bh[gB * 2 + 1][0] = t1;
                bh[gB * 2][1] = t2; bh[gB * 2 + 1][1] = t3;
                ldsm_x4(t0, t1, t2, t3, sBl + d);
                bl[gB * 2][0] = t0; bl[gB * 2 + 1][0] = t1;
                bl[gB * 2][1] = t2; bl[gB * 2 + 1][1] = t3;
            }
            #pragma unroll
            for (int f = 0; f < 2; f++)
                #pragma unroll
                for (int nf = 0; nf < 8; nf++) {
                    mma_bf16(acc[f][nf], ah[f], bh[nf]);
                    mma_bf16(acc[f][nf], ah[f], bl[nf]);
                    mma_bf16(acc[f][nf], al[f], bh[nf]);
                }
        }
        __syncthreads();
    }

    // Epilogue: bias add + store. c0,c1 -> row g, cols tg*2..+1; c2,c3 -> row g+8.
    const int g  = lid >> 2;
    const int tg = lid & 3;
    float2 bias[8];
    #pragma unroll
    for (int nf = 0; nf < 8; nf++) {
        const int v = vtile * 128 + warpN * 64 + nf * 8 + tg * 2;
        bias[nf] = *reinterpret_cast<const float2*>(pred_b + n * VV + v);
    }
    #pragma unroll
    for (int f = 0; f < 2; f++) {
        const int m0 = mtile * 128 + warpM * 32 + f * 16 + g;
        #pragma unroll
        for (int nf = 0; nf < 8; nf++) {
            const int v = vtile * 128 + warpN * 64 + nf * 8 + tg * 2;
            float* o0 = out + ((size_t)m0 * NN + n) * VV + v;
            float* o1 = out + ((size_t)(m0 + 8) * NN + n) * VV + v;
            float2 r0 = make_float2(acc[f][nf][0] + bias[nf].x, acc[f][nf][1] + bias[nf].y);
            float2 r1 = make_float2(acc[f][nf][2] + bias[nf].x, acc[f][nf][3] + bias[nf].y);
            *reinterpret_cast<float2*>(o0) = r0;
            *reinterpret_cast<float2*>(o1) = r1;
        }
    }
}

// ---------------------------------------------------------------------------
extern "C" void kernel_launch(void* const* d_in, const int* in_sizes, int n_in,
                              void* d_out, int out_size)
{
    const float* input_embedding = (const float*)d_in[0];  // (B, H)
    const int*   features        = (const int*)d_in[1];    // (B, N)
    const float* emb_tables      = (const float*)d_in[2];  // (N, V, H)
    const float* ln_gamma        = (const float*)d_in[3];  // (2H,)
    const float* ln_beta         = (const float*)d_in[4];  // (2H,)
    const float* pred_W          = (const float*)d_in[5];  // (N, 2H, V)
    const float* pred_b          = (const float*)d_in[6];  // (N, V)
    float* out = (float*)d_out;                            // (B, N, V)

    cudaFuncSetAttribute(gemm_mma_kernel,
                         cudaFuncAttributeMaxDynamicSharedMemorySize, GEMM_DYN_SMEM);

    wconv_kernel<<<dim3(TWO_H / 32, VV / 32, NN), dim3(32, 8)>>>(pred_W);
    act_kernel<<<BB, 256>>>(input_embedding, features, emb_tables, ln_gamma, ln_beta);
    gemm_mma_kernel<<<dim3(2, 64, NN), 256, GEMM_DYN_SMEM>>>(pred_b, out);
}

// round 4
// speedup vs baseline: 3.1283x; 1.4760x over previous
#include <cuda_runtime.h>
#include <cuda_fp16.h>
#include <math.h>
#include <stdint.h>

// Problem constants
#define BB 8192
#define NN 12
#define HH 512
#define TWO_H 1024
#define VV 256
#define LN_EPS 1e-5f

// ---------------------------------------------------------------------------
// Device scratch: fp16 activations (hi only) + W^T hi/lo fp16
// ---------------------------------------------------------------------------
__device__ __align__(1024) __half g_a_hi[(size_t)NN * BB * TWO_H];
__device__ __align__(1024) __half g_w_hi[(size_t)NN * VV * TWO_H];
__device__ __align__(1024) __half g_w_lo[(size_t)NN * VV * TWO_H];

// ---------------------------------------------------------------------------
// PTX helpers (base-PTX only: cp.async, ldmatrix, mma.sync — all sm_80+)
// ---------------------------------------------------------------------------
__device__ __forceinline__ uint32_t smem_u32(const void* p) {
    uint32_t a;
    asm("{ .reg .u64 t; cvta.to.shared.u64 t, %1; cvt.u32.u64 %0, t; }" : "=r"(a) : "l"(p));
    return a;
}
__device__ __forceinline__ void cp_async16(uint32_t dst, const void* src) {
    asm volatile("cp.async.cg.shared.global [%0], [%1], 16;" :: "r"(dst), "l"(src) : "memory");
}
#define CP_ASYNC_COMMIT() asm volatile("cp.async.commit_group;" ::: "memory")

__device__ __forceinline__ void ldsm_x4(uint32_t& r0, uint32_t& r1, uint32_t& r2, uint32_t& r3,
                                        uint32_t addr) {
    asm volatile("ldmatrix.sync.aligned.m8n8.x4.shared.b16 {%0,%1,%2,%3}, [%4];"
                 : "=r"(r0), "=r"(r1), "=r"(r2), "=r"(r3) : "r"(addr));
}
__device__ __forceinline__ void mma_f16(float* d, const uint32_t* a, const uint32_t* b) {
    asm volatile(
        "mma.sync.aligned.m16n8k16.row.col.f32.f16.f16.f32 "
        "{%0,%1,%2,%3}, {%4,%5,%6,%7}, {%8,%9}, {%0,%1,%2,%3};"
        : "+f"(d[0]), "+f"(d[1]), "+f"(d[2]), "+f"(d[3])
        : "r"(a[0]), "r"(a[1]), "r"(a[2]), "r"(a[3]), "r"(b[0]), "r"(b[1]));
}

#define SWZ128(o) ((o) ^ (((o) >> 3) & 0x70))

__device__ __forceinline__ void split_f16(float a, __half& hi, __half& lo) {
    hi = __float2half(a);
    lo = __float2half(a - __half2float(hi));
}

// ---------------------------------------------------------------------------
// Kernel 1: gather + exclusive prefix sum + LayerNorm + exact GELU -> fp16
// One CTA per batch row b. 256 threads x 4 dims each.
// ---------------------------------------------------------------------------
__global__ void __launch_bounds__(256) act_kernel(
    const float* __restrict__ input_embedding,  // (B, H)
    const int* __restrict__ features,           // (B, N)
    const float* __restrict__ emb_tables,       // (N, V, H)
    const float* __restrict__ ln_gamma,         // (2H,)
    const float* __restrict__ ln_beta)          // (2H,)
{
    const int b = blockIdx.x;
    const int tid = threadIdx.x;
    const int i = tid * 4;
    const bool is_ctx = (tid < 128);

    __shared__ float sh_s[8];
    __shared__ float sh_q[8];
    __shared__ float sh_mu, sh_rstd;

    float4 vals;
    if (is_ctx) {
        vals = *reinterpret_cast<const float4*>(input_embedding + (size_t)b * HH + i);
    } else {
        vals = make_float4(0.f, 0.f, 0.f, 0.f);
    }
    const float4 g  = *reinterpret_cast<const float4*>(ln_gamma + i);
    const float4 be = *reinterpret_cast<const float4*>(ln_beta + i);

    const float inv = 1.0f / (float)TWO_H;

    for (int n = 0; n < NN; n++) {
        float s1 = vals.x + vals.y + vals.z + vals.w;
        float s2 = vals.x * vals.x + vals.y * vals.y + vals.z * vals.z + vals.w * vals.w;
        #pragma unroll
        for (int o = 16; o > 0; o >>= 1) {
            s1 += __shfl_xor_sync(0xFFFFFFFFu, s1, o);
            s2 += __shfl_xor_sync(0xFFFFFFFFu, s2, o);
        }
        if ((tid & 31) == 0) { sh_s[tid >> 5] = s1; sh_q[tid >> 5] = s2; }
        __syncthreads();
        if (tid == 0) {
            float ta = 0.f, tb = 0.f;
            #pragma unroll
            for (int w = 0; w < 8; w++) { ta += sh_s[w]; tb += sh_q[w]; }
            float mu  = ta * inv;
            float var = tb * inv - mu * mu;
            sh_mu = mu;
            sh_rstd = rsqrtf(var + LN_EPS);
        }
        __syncthreads();
        const float mu = sh_mu, rstd = sh_rstd;

        float yv[4] = {vals.x, vals.y, vals.z, vals.w};
        float gv[4] = {g.x, g.y, g.z, g.w};
        float bv[4] = {be.x, be.y, be.z, be.w};
        __half h4[4];
        #pragma unroll
        for (int j = 0; j < 4; j++) {
            float y = (yv[j] - mu) * rstd * gv[j] + bv[j];
            float a = 0.5f * y * (1.0f + erff(y * 0.70710678118654752f));
            h4[j] = __float2half(a);
        }
        const size_t ofs = ((size_t)n * BB + b) * TWO_H + i;
        *reinterpret_cast<uint2*>(g_a_hi + ofs) = *reinterpret_cast<uint2*>(h4);

        if (!is_ctx) {
            const int feat = features[b * NN + n];
            const float4 e = *reinterpret_cast<const float4*>(
                emb_tables + ((size_t)n * VV + feat) * HH + (i - HH));
            vals.x += e.x; vals.y += e.y; vals.z += e.z; vals.w += e.w;
        }
    }
}

// ---------------------------------------------------------------------------
// Kernel 2: transpose + fp16-split pred_W (N,2H,V) -> W^T hi/lo (N,V,2H)
// ---------------------------------------------------------------------------
__global__ void __launch_bounds__(256) wconv_kernel(const float* __restrict__ pred_W)
{
    __shared__ float tile[32][33];
    const int n  = blockIdx.z;
    const int k0 = blockIdx.x * 32;
    const int v0 = blockIdx.y * 32;
    const int tx = threadIdx.x, ty = threadIdx.y;

    #pragma unroll
    for (int r = 0; r < 4; r++) {
        const int k = k0 + ty + r * 8;
        tile[ty + r * 8][tx] = pred_W[((size_t)n * TWO_H + k) * VV + v0 + tx];
    }
    __syncthreads();
    #pragma unroll
    for (int r = 0; r < 4; r++) {
        const int v = v0 + ty + r * 8;
        const float w = tile[tx][ty + r * 8];
        __half hi, lo;
        split_f16(w, hi, lo);
        const size_t idx = ((size_t)n * VV + v) * TWO_H + k0 + tx;
        g_w_hi[idx] = hi;
        g_w_lo[idx] = lo;
    }
}

// ---------------------------------------------------------------------------
// Kernel 3: mma.sync fp16 GEMM, 2-term split: C = Ah*(Wh + Wl), fp32 accum.
// CTA tile 128(M)x128(N), K-chunk 64, double-buffered cp.async, 2 CTAs/SM.
// 8 warps: warpM = wid&3 (32 rows), warpN = wid>>2 (64 cols).
// ---------------------------------------------------------------------------
#define KCH 64
#define NCHUNK (TWO_H / KCH)            // 16
#define TILE_BYTES (128 * 128)          // 16KB each (128 rows x 64 fp16)
#define STAGE_BYTES (3 * TILE_BYTES)    // Ah, Wh, Wl = 48KB
#define GEMM_DYN_SMEM (2 * STAGE_BYTES) // 96KB

__global__ void __launch_bounds__(256, 2) gemm_mma_kernel(
    const float* __restrict__ pred_b,   // (N, V)
    float* __restrict__ out)            // (B, N, V)
{
    extern __shared__ __align__(1024) char dynsmem[];
    const int vtile = blockIdx.x;       // 0..1
    const int mtile = blockIdx.y;       // 0..63
    const int n     = blockIdx.z;       // 0..11
    const int tid = threadIdx.x;
    const int wid = tid >> 5;
    const int lid = tid & 31;
    const int warpM = wid & 3;          // 0..3 -> 32 rows
    const int warpN = wid >> 2;         // 0..1 -> 64 cols

    const uint32_t base = smem_u32(dynsmem);

    const __half* Ah = g_a_hi + ((size_t)n * BB + (size_t)mtile * 128) * TWO_H;
    const __half* Wh = g_w_hi + ((size_t)n * VV + (size_t)vtile * 128) * TWO_H;
    const __half* Wl = g_w_lo + ((size_t)n * VV + (size_t)vtile * 128) * TWO_H;

    // cp.async indexing: each 16KB tile = 128 rows x 8 segs of 16B.
    const int l_row[4] = { (0 * 256 + tid) >> 3, (1 * 256 + tid) >> 3,
                           (2 * 256 + tid) >> 3, (3 * 256 + tid) >> 3 };
    const int l_seg = tid & 7;

    float acc[2][8][4];
    #pragma unroll
    for (int f = 0; f < 2; f++)
        #pragma unroll
        for (int nf = 0; nf < 8; nf++)
            #pragma unroll
            for (int j = 0; j < 4; j++) acc[f][nf][j] = 0.f;

    const int lrow = lid & 15;
    const int khalf = lid >> 4;

    #define LOAD_STAGE(c, buf) do { \
        const uint32_t sA  = base + (buf) * STAGE_BYTES; \
        const uint32_t sWh = sA + TILE_BYTES; \
        const uint32_t sWl = sWh + TILE_BYTES; \
        const int kofs = (c) * KCH; \
        _Pragma("unroll") \
        for (int t = 0; t < 4; t++) { \
            const int row = l_row[t]; \
            const uint32_t d = SWZ128(row * 128 + l_seg * 16); \
            const size_t go = (size_t)row * TWO_H + kofs + l_seg * 8; \
            cp_async16(sA  + d, Ah + go); \
            cp_async16(sWh + d, Wh + go); \
            cp_async16(sWl + d, Wl + go); \
        } \
        CP_ASYNC_COMMIT(); \
    } while (0)

    LOAD_STAGE(0, 0);

    for (int c = 0; c < NCHUNK; c++) {
        if (c + 1 < NCHUNK) {
            LOAD_STAGE(c + 1, (c + 1) & 1);
            asm volatile("cp.async.wait_group 1;" ::: "memory");
        } else {
            asm volatile("cp.async.wait_group 0;" ::: "memory");
        }
        __syncthreads();

        const uint32_t sA  = base + (c & 1) * STAGE_BYTES;
        const uint32_t sWh = sA + TILE_BYTES;
        const uint32_t sWl = sWh + TILE_BYTES;

        #pragma unroll
        for (int ks = 0; ks < 4; ks++) {
            uint32_t ah[2][4], bh[8][2], bl[8][2];
            #pragma unroll
            for (int f = 0; f < 2; f++) {
                const int row = warpM * 32 + f * 16 + lrow;
                const uint32_t d = SWZ128(row * 128 + ks * 32 + khalf * 16);
                ldsm_x4(ah[f][0], ah[f][1], ah[f][2], ah[f][3], sA + d);
            }
            #pragma unroll
            for (int gB = 0; gB < 4; gB++) {
                const int row = warpN * 64 + gB * 16 + lrow;
                const uint32_t d = SWZ128(row * 128 + ks * 32 + khalf * 16);
                uint32_t t0, t1, t2, t3;
                ldsm_x4(t0, t1, t2, t3, sWh + d);
                bh[gB * 2][0] = t0; bh[gB * 2 + 1][0] = t1;
                bh[gB * 2][1] = t2; bh[gB * 2 + 1][1] = t3;
                ldsm_x4(t0, t1, t2, t3, sWl + d);
                bl[gB * 2][0] = t0; bl[gB * 2 + 1][0] = t1;
                bl[gB * 2][1] = t2; bl[gB * 2 + 1][1] = t3;
            }
            #pragma unroll
            for (int f = 0; f < 2; f++)
                #pragma unroll
                for (int nf = 0; nf < 8; nf++) {
                    mma_f16(acc[f][nf], ah[f], bh[nf]);
                    mma_f16(acc[f][nf], ah[f], bl[nf]);
                }
        }
        __syncthreads();
    }

    // Epilogue: bias add + store.
    const int g  = lid >> 2;
    const int tg = lid & 3;
    float2 bias[8];
    #pragma unroll
    for (int nf = 0; nf < 8; nf++) {
        const int v = vtile * 128 + warpN * 64 + nf * 8 + tg * 2;
        bias[nf] = *reinterpret_cast<const float2*>(pred_b + n * VV + v);
    }
    #pragma unroll
    for (int f = 0; f < 2; f++) {
        const int m0 = mtile * 128 + warpM * 32 + f * 16 + g;
        #pragma unroll
        for (int nf = 0; nf < 8; nf++) {
            const int v = vtile * 128 + warpN * 64 + nf * 8 + tg * 2;
            float* o0 = out + ((size_t)m0 * NN + n) * VV + v;
            float* o1 = out + ((size_t)(m0 + 8) * NN + n) * VV + v;
            float2 r0 = make_float2(acc[f][nf][0] + bias[nf].x, acc[f][nf][1] + bias[nf].y);
            float2 r1 = make_float2(acc[f][nf][2] + bias[nf].x, acc[f][nf][3] + bias[nf].y);
            *reinterpret_cast<float2*>(o0) = r0;
            *reinterpret_cast<float2*>(o1) = r1;
        }
    }
}

// ---------------------------------------------------------------------------
extern "C" void kernel_launch(void* const* d_in, const int* in_sizes, int n_in,
                              void* d_out, int out_size)
{
    const float* input_embedding = (const float*)d_in[0];  // (B, H)
    const int*   features        = (const int*)d_in[1];    // (B, N)
    const float* emb_tables      = (const float*)d_in[2];  // (N, V, H)
    const float* ln_gamma        = (const float*)d_in[3];  // (2H,)
    const float* ln_beta         = (const float*)d_in[4];  // (2H,)
    const float* pred_W          = (const float*)d_in[5];  // (N, 2H, V)
    const float* pred_b          = (const float*)d_in[6];  // (N, V)
    float* out = (float*)d_out;                            // (B, N, V)

    cudaFuncSetAttribute(gemm_mma_kernel,
                         cudaFuncAttributeMaxDynamicSharedMemorySize, GEMM_DYN_SMEM);

    wconv_kernel<<<dim3(TWO_H / 32, VV / 32, NN), dim3(32, 8)>>>(pred_W);
    act_kernel<<<BB, 256>>>(input_embedding, features, emb_tables, ln_gamma, ln_beta);
    gemm_mma_kernel<<<dim3(2, 64, NN), 256, GEMM_DYN_SMEM>>>(pred_b, out);
}

// round 5
// speedup vs baseline: 4.2779x; 1.3675x over previous
#include <cuda_runtime.h>
#include <cuda_fp16.h>
#include <math.h>
#include <stdint.h>

// Problem constants
#define BB 8192
#define NN 12
#define HH 512
#define TWO_H 1024
#define VV 256
#define LN_EPS 1e-5f

// ---------------------------------------------------------------------------
// Device scratch: fp16 activations + fp16 W^T
// ---------------------------------------------------------------------------
__device__ __align__(1024) __half g_a[(size_t)NN * BB * TWO_H];
__device__ __align__(1024) __half g_w[(size_t)NN * VV * TWO_H];

// ---------------------------------------------------------------------------
// PTX helpers (base-PTX only: cp.async, ldmatrix, mma.sync — all sm_80+)
// ---------------------------------------------------------------------------
__device__ __forceinline__ uint32_t smem_u32(const void* p) {
    uint32_t a;
    asm("{ .reg .u64 t; cvta.to.shared.u64 t, %1; cvt.u32.u64 %0, t; }" : "=r"(a) : "l"(p));
    return a;
}
__device__ __forceinline__ void cp_async16(uint32_t dst, const void* src) {
    asm volatile("cp.async.cg.shared.global [%0], [%1], 16;" :: "r"(dst), "l"(src) : "memory");
}
#define CP_ASYNC_COMMIT() asm volatile("cp.async.commit_group;" ::: "memory")

__device__ __forceinline__ void ldsm_x4(uint32_t& r0, uint32_t& r1, uint32_t& r2, uint32_t& r3,
                                        uint32_t addr) {
    asm volatile("ldmatrix.sync.aligned.m8n8.x4.shared.b16 {%0,%1,%2,%3}, [%4];"
                 : "=r"(r0), "=r"(r1), "=r"(r2), "=r"(r3) : "r"(addr));
}
__device__ __forceinline__ void mma_f16(float* d, const uint32_t* a, const uint32_t* b) {
    asm volatile(
        "mma.sync.aligned.m16n8k16.row.col.f32.f16.f16.f32 "
        "{%0,%1,%2,%3}, {%4,%5,%6,%7}, {%8,%9}, {%0,%1,%2,%3};"
        : "+f"(d[0]), "+f"(d[1]), "+f"(d[2]), "+f"(d[3])
        : "r"(a[0]), "r"(a[1]), "r"(a[2]), "r"(a[3]), "r"(b[0]), "r"(b[1]));
}

#define SWZ128(o) ((o) ^ (((o) >> 3) & 0x70))

// ---------------------------------------------------------------------------
// Kernel 1: gather + exclusive prefix sum + LayerNorm + exact GELU -> fp16
// One CTA per batch row b. 256 threads x 4 dims each.
// ---------------------------------------------------------------------------
__global__ void __launch_bounds__(256) act_kernel(
    const float* __restrict__ input_embedding,  // (B, H)
    const int* __restrict__ features,           // (B, N)
    const float* __restrict__ emb_tables,       // (N, V, H)
    const float* __restrict__ ln_gamma,         // (2H,)
    const float* __restrict__ ln_beta)          // (2H,)
{
    const int b = blockIdx.x;
    const int tid = threadIdx.x;
    const int i = tid * 4;
    const bool is_ctx = (tid < 128);

    __shared__ float sh_s[8];
    __shared__ float sh_q[8];
    __shared__ float sh_mu, sh_rstd;

    float4 vals;
    if (is_ctx) {
        vals = *reinterpret_cast<const float4*>(input_embedding + (size_t)b * HH + i);
    } else {
        vals = make_float4(0.f, 0.f, 0.f, 0.f);
    }
    const float4 g  = *reinterpret_cast<const float4*>(ln_gamma + i);
    const float4 be = *reinterpret_cast<const float4*>(ln_beta + i);

    const float inv = 1.0f / (float)TWO_H;

    for (int n = 0; n < NN; n++) {
        float s1 = vals.x + vals.y + vals.z + vals.w;
        float s2 = vals.x * vals.x + vals.y * vals.y + vals.z * vals.z + vals.w * vals.w;
        #pragma unroll
        for (int o = 16; o > 0; o >>= 1) {
            s1 += __shfl_xor_sync(0xFFFFFFFFu, s1, o);
            s2 += __shfl_xor_sync(0xFFFFFFFFu, s2, o);
        }
        if ((tid & 31) == 0) { sh_s[tid >> 5] = s1; sh_q[tid >> 5] = s2; }
        __syncthreads();
        if (tid == 0) {
            float ta = 0.f, tb = 0.f;
            #pragma unroll
            for (int w = 0; w < 8; w++) { ta += sh_s[w]; tb += sh_q[w]; }
            float mu  = ta * inv;
            float var = tb * inv - mu * mu;
            sh_mu = mu;
            sh_rstd = rsqrtf(var + LN_EPS);
        }
        __syncthreads();
        const float mu = sh_mu, rstd = sh_rstd;

        float yv[4] = {vals.x, vals.y, vals.z, vals.w};
        float gv[4] = {g.x, g.y, g.z, g.w};
        float bv[4] = {be.x, be.y, be.z, be.w};
        __half h4[4];
        #pragma unroll
        for (int j = 0; j < 4; j++) {
            float y = (yv[j] - mu) * rstd * gv[j] + bv[j];
            float a = 0.5f * y * (1.0f + erff(y * 0.70710678118654752f));
            h4[j] = __float2half(a);
        }
        const size_t ofs = ((size_t)n * BB + b) * TWO_H + i;
        *reinterpret_cast<uint2*>(g_a + ofs) = *reinterpret_cast<uint2*>(h4);

        if (!is_ctx) {
            const int feat = features[b * NN + n];
            const float4 e = *reinterpret_cast<const float4*>(
                emb_tables + ((size_t)n * VV + feat) * HH + (i - HH));
            vals.x += e.x; vals.y += e.y; vals.z += e.z; vals.w += e.w;
        }
    }
}

// ---------------------------------------------------------------------------
// Kernel 2: transpose + fp16 convert pred_W (N,2H,V) -> W^T (N,V,2H)
// ---------------------------------------------------------------------------
__global__ void __launch_bounds__(256) wconv_kernel(const float* __restrict__ pred_W)
{
    __shared__ float tile[32][33];
    const int n  = blockIdx.z;
    const int k0 = blockIdx.x * 32;
    const int v0 = blockIdx.y * 32;
    const int tx = threadIdx.x, ty = threadIdx.y;

    #pragma unroll
    for (int r = 0; r < 4; r++) {
        const int k = k0 + ty + r * 8;
        tile[ty + r * 8][tx] = pred_W[((size_t)n * TWO_H + k) * VV + v0 + tx];
    }
    __syncthreads();
    #pragma unroll
    for (int r = 0; r < 4; r++) {
        const int v = v0 + ty + r * 8;
        const float w = tile[tx][ty + r * 8];
        g_w[((size_t)n * VV + v) * TWO_H + k0 + tx] = __float2half(w);
    }
}

// ---------------------------------------------------------------------------
// Kernel 3: mma.sync fp16 GEMM, single term: C = A*W^T, fp32 accum.
// CTA tile 128(M)x128(N), K-chunk 64, double-buffered cp.async, 2 CTAs/SM.
// 8 warps: warpM = wid&3 (32 rows), warpN = wid>>2 (64 cols).
// ---------------------------------------------------------------------------
#define KCH 64
#define NCHUNK (TWO_H / KCH)            // 16
#define TILE_BYTES (128 * 128)          // 16KB each (128 rows x 64 fp16)
#define STAGE_BYTES (2 * TILE_BYTES)    // A, W = 32KB
#define GEMM_DYN_SMEM (2 * STAGE_BYTES) // 64KB

__global__ void __launch_bounds__(256, 2) gemm_mma_kernel(
    const float* __restrict__ pred_b,   // (N, V)
    float* __restrict__ out)            // (B, N, V)
{
    extern __shared__ __align__(1024) char dynsmem[];
    const int vtile = blockIdx.x;       // 0..1
    const int mtile = blockIdx.y;       // 0..63
    const int n     = blockIdx.z;       // 0..11
    const int tid = threadIdx.x;
    const int wid = tid >> 5;
    const int lid = tid & 31;
    const int warpM = wid & 3;          // 0..3 -> 32 rows
    const int warpN = wid >> 2;         // 0..1 -> 64 cols

    const uint32_t base = smem_u32(dynsmem);

    const __half* A = g_a + ((size_t)n * BB + (size_t)mtile * 128) * TWO_H;
    const __half* W = g_w + ((size_t)n * VV + (size_t)vtile * 128) * TWO_H;

    // cp.async indexing: each 16KB tile = 128 rows x 8 segs of 16B.
    const int l_row[4] = { (0 * 256 + tid) >> 3, (1 * 256 + tid) >> 3,
                           (2 * 256 + tid) >> 3, (3 * 256 + tid) >> 3 };
    const int l_seg = tid & 7;

    float acc[2][8][4];
    #pragma unroll
    for (int f = 0; f < 2; f++)
        #pragma unroll
        for (int nf = 0; nf < 8; nf++)
            #pragma unroll
            for (int j = 0; j < 4; j++) acc[f][nf][j] = 0.f;

    const int lrow = lid & 15;
    const int khalf = lid >> 4;

    #define LOAD_STAGE(c, buf) do { \
        const uint32_t sA = base + (buf) * STAGE_BYTES; \
        const uint32_t sW = sA + TILE_BYTES; \
        const int kofs = (c) * KCH; \
        _Pragma("unroll") \
        for (int t = 0; t < 4; t++) { \
            const int row = l_row[t]; \
            const uint32_t d = SWZ128(row * 128 + l_seg * 16); \
            const size_t go = (size_t)row * TWO_H + kofs + l_seg * 8; \
            cp_async16(sA + d, A + go); \
            cp_async16(sW + d, W + go); \
        } \
        CP_ASYNC_COMMIT(); \
    } while (0)

    LOAD_STAGE(0, 0);

    for (int c = 0; c < NCHUNK; c++) {
        if (c + 1 < NCHUNK) {
            LOAD_STAGE(c + 1, (c + 1) & 1);
            asm volatile("cp.async.wait_group 1;" ::: "memory");
        } else {
            asm volatile("cp.async.wait_group 0;" ::: "memory");
        }
        __syncthreads();

        const uint32_t sA = base + (c & 1) * STAGE_BYTES;
        const uint32_t sW = sA + TILE_BYTES;

        #pragma unroll
        for (int ks = 0; ks < 4; ks++) {
            uint32_t ah[2][4], bh[8][2];
            #pragma unroll
            for (int f = 0; f < 2; f++) {
                const int row = warpM * 32 + f * 16 + lrow;
                const uint32_t d = SWZ128(row * 128 + ks * 32 + khalf * 16);
                ldsm_x4(ah[f][0], ah[f][1], ah[f][2], ah[f][3], sA + d);
            }
            #pragma unroll
            for (int gB = 0; gB < 4; gB++) {
                const int row = warpN * 64 + gB * 16 + lrow;
                const uint32_t d = SWZ128(row * 128 + ks * 32 + khalf * 16);
                uint32_t t0, t1, t2, t3;
                ldsm_x4(t0, t1, t2, t3, sW + d);
                bh[gB * 2][0] = t0; bh[gB * 2 + 1][0] = t1;
                bh[gB * 2][1] = t2; bh[gB * 2 + 1][1] = t3;
            }
            #pragma unroll
            for (int f = 0; f < 2; f++)
                #pragma unroll
                for (int nf = 0; nf < 8; nf++)
                    mma_f16(acc[f][nf], ah[f], bh[nf]);
        }
        __syncthreads();
    }

    // Epilogue: bias add + store.
    const int g  = lid >> 2;
    const int tg = lid & 3;
    float2 bias[8];
    #pragma unroll
    for (int nf = 0; nf < 8; nf++) {
        const int v = vtile * 128 + warpN * 64 + nf * 8 + tg * 2;
        bias[nf] = *reinterpret_cast<const float2*>(pred_b + n * VV + v);
    }
    #pragma unroll
    for (int f = 0; f < 2; f++) {
        const int m0 = mtile * 128 + warpM * 32 + f * 16 + g;
        #pragma unroll
        for (int nf = 0; nf < 8; nf++) {
            const int v = vtile * 128 + warpN * 64 + nf * 8 + tg * 2;
            float* o0 = out + ((size_t)m0 * NN + n) * VV + v;
            float* o1 = out + ((size_t)(m0 + 8) * NN + n) * VV + v;
            float2 r0 = make_float2(acc[f][nf][0] + bias[nf].x, acc[f][nf][1] + bias[nf].y);
            float2 r1 = make_float2(acc[f][nf][2] + bias[nf].x, acc[f][nf][3] + bias[nf].y);
            *reinterpret_cast<float2*>(o0) = r0;
            *reinterpret_cast<float2*>(o1) = r1;
        }
    }
}

// ---------------------------------------------------------------------------
extern "C" void kernel_launch(void* const* d_in, const int* in_sizes, int n_in,
                              void* d_out, int out_size)
{
    const float* input_embedding = (const float*)d_in[0];  // (B, H)
    const int*   features        = (const int*)d_in[1];    // (B, N)
    const float* emb_tables      = (const float*)d_in[2];  // (N, V, H)
    const float* ln_gamma        = (const float*)d_in[3];  // (2H,)
    const float* ln_beta         = (const float*)d_in[4];  // (2H,)
    const float* pred_W          = (const float*)d_in[5];  // (N, 2H, V)
    const float* pred_b          = (const float*)d_in[6];  // (N, V)
    float* out = (float*)d_out;                            // (B, N, V)

    cudaFuncSetAttribute(gemm_mma_kernel,
                         cudaFuncAttributeMaxDynamicSharedMemorySize, GEMM_DYN_SMEM);

    wconv_kernel<<<dim3(TWO_H / 32, VV / 32, NN), dim3(32, 8)>>>(pred_W);
    act_kernel<<<BB, 256>>>(input_embedding, features, emb_tables, ln_gamma, ln_beta);
    gemm_mma_kernel<<<dim3(2, 64, NN), 256, GEMM_DYN_SMEM>>>(pred_b, out);
}